// round 5
// baseline (speedup 1.0000x reference)
#include <cuda_runtime.h>

#define D 64
#define NMAX 150016          // max total nodes (100000 + 50000, padded)
#define RPB 64               // rows per block in fused kernel
#define TPB 256              // threads per block in fused kernel (8 warps)

// Scratch: static device globals (module-load allocation, allowed by harness rules)
__device__ float g_E[NMAX * D];     // current layer embeddings (unnormalized)
__device__ float g_agg[NMAX * D];   // edge aggregation accumulator

__device__ __forceinline__ float lrelu(float x) {
    return x > 0.0f ? x : 0.01f * x;
}

// E0 = concat(user, item); write raw E0 into out[:, 0:64]; zero g_agg (first-run init)
__global__ void init_kernel(const float* __restrict__ user, const float* __restrict__ item,
                            float* __restrict__ out, int n_user, int n_total) {
    int t = blockIdx.x * blockDim.x + threadIdx.x;
    if (t >= n_total * (D / 4)) return;
    int row = t >> 4;
    int c = (t & 15) * 4;
    float4 v;
    if (row < n_user) v = *(const float4*)&user[row * D + c];
    else              v = *(const float4*)&item[(row - n_user) * D + c];
    *(float4*)&g_E[row * D + c] = v;
    *(float4*)&g_agg[row * D + c] = make_float4(0.f, 0.f, 0.f, 0.f);
    __stcs((float4*)&out[row * 4 * D + c], v);
}

// agg[row] += val * E[col] per edge. 16 threads (half-warp) per edge, one float4 each.
// Edge scalars loaded once per half-warp, broadcast via shfl.
__global__ void scatter_kernel(const int* __restrict__ erow, const int* __restrict__ ecol,
                               const float* __restrict__ eval, int nE) {
    int t = blockIdx.x * blockDim.x + threadIdx.x;
    int e = t >> 4;
    int lane = threadIdx.x & 31;
    int src = lane & 16;                 // leader lane of this half-warp
    int r = 0, cl = 0; float v = 0.f;
    if ((lane & 15) == 0 && e < nE) { r = erow[e]; cl = ecol[e]; v = eval[e]; }
    r  = __shfl_sync(0xffffffffu, r,  src);
    cl = __shfl_sync(0xffffffffu, cl, src);
    v  = __shfl_sync(0xffffffffu, v,  src);
    if (e >= nE) return;
    int c = (t & 15) * 4;
    float4 x = *(const float4*)&g_E[cl * D + c];
    float4 m = make_float4(v * x.x, v * x.y, v * x.z, v * x.w);
    atomicAdd((float4*)&g_agg[r * D + c], m);   // vectorized RED (sm_90+)
}

// Per row n:
//   f  = agg[n] + E[n]   (+I folded);  agg zeroed in-place for next layer
//   t  = lrelu(f @ Wf^T + bf);  u = lrelu((E[n]*f) @ Wb^T + bb)
//   Enew = t + u -> g_E (if writeE), out[n, out_col:+64] = Enew/||Enew||
// Block: 64 rows, 256 threads. Warp w: rows w*8 + (lane/16)*4 .. +3.
// Thread: R=4 rows x C=4 cols (cols c0, c0+16, c0+32, c0+48; c0 = lane%16).
__global__ void __launch_bounds__(TPB)
fused_kernel(const float* __restrict__ Wf, const float* __restrict__ bfv,
             const float* __restrict__ Wb, const float* __restrict__ bbv,
             float* __restrict__ out, int out_col, int n_total, int writeE) {
    extern __shared__ float sm[];
    float* Wfs = sm;               // [j][k] stride 68 -> conflict-free float4 reads along k
    float* Wbs = Wfs + 64 * 68;
    float* fs  = Wbs + 64 * 68;    // [k][r] stride 68 -> 2-address broadcast LDS.128
    float* efs = fs + 64 * 68;

    int tid  = threadIdx.x;
    int lane = tid & 31;
    int w    = tid >> 5;           // 0..7
    int base = blockIdx.x * RPB;

    // Stage weights (global [j][k] row-major; out[n,j] = sum_k x[n,k]*W[j,k])
    for (int idx = tid; idx < 4096; idx += TPB) {
        int j = idx >> 6, k = idx & 63;
        Wfs[j * 68 + k] = Wf[idx];
        Wbs[j * 68 + k] = Wb[idx];
    }
    // Stage rows: f = agg+E, ef = E*f; zero agg in place (replaces zero_kernel)
    for (int idx = tid; idx < 4096; idx += TPB) {
        int r = idx >> 6, k = idx & 63;
        int row = base + r;
        float e = 0.f, a = 0.f;
        if (row < n_total) {
            e = g_E[row * D + k];
            a = g_agg[row * D + k];
            g_agg[row * D + k] = 0.f;
        }
        float f = a + e;
        fs[k * 68 + r]  = f;
        efs[k * 68 + r] = e * f;
    }
    __syncthreads();

    int c0 = lane & 15;
    int h  = lane >> 4;
    int r0 = w * 8 + h * 4;
    int cols[4] = {c0, c0 + 16, c0 + 32, c0 + 48};

    float af[4][4], ab[4][4];
    #pragma unroll
    for (int c = 0; c < 4; c++) {
        float bfc = bfv[cols[c]], bbc = bbv[cols[c]];
        #pragma unroll
        for (int r = 0; r < 4; r++) { af[r][c] = bfc; ab[r][c] = bbc; }
    }

    #pragma unroll
    for (int k = 0; k < 64; k += 4) {
        float4 wf[4], wb[4];
        #pragma unroll
        for (int c = 0; c < 4; c++) {
            wf[c] = *(float4*)&Wfs[cols[c] * 68 + k];
            wb[c] = *(float4*)&Wbs[cols[c] * 68 + k];
        }
        #pragma unroll
        for (int kk = 0; kk < 4; kk++) {
            float4 f  = *(float4*)&fs[(k + kk) * 68 + r0];
            float4 ef = *(float4*)&efs[(k + kk) * 68 + r0];
            #pragma unroll
            for (int c = 0; c < 4; c++) {
                float a = (&wf[c].x)[kk];
                float b = (&wb[c].x)[kk];
                af[0][c] += f.x * a;   ab[0][c] += ef.x * b;
                af[1][c] += f.y * a;   ab[1][c] += ef.y * b;
                af[2][c] += f.z * a;   ab[2][c] += ef.z * b;
                af[3][c] += f.w * a;   ab[3][c] += ef.w * b;
            }
        }
    }

    // Epilogue: leaky-relu, sum, row-norm (16 col-lanes of each half cover all 64 cols)
    float ev[4][4];
    float s[4] = {0.f, 0.f, 0.f, 0.f};
    #pragma unroll
    for (int r = 0; r < 4; r++) {
        #pragma unroll
        for (int c = 0; c < 4; c++) {
            float x = lrelu(af[r][c]) + lrelu(ab[r][c]);
            ev[r][c] = x;
            s[r] += x * x;
        }
    }
    #pragma unroll
    for (int r = 0; r < 4; r++) {
        #pragma unroll
        for (int o = 1; o < 16; o <<= 1)
            s[r] += __shfl_xor_sync(0xffffffffu, s[r], o);
    }
    #pragma unroll
    for (int r = 0; r < 4; r++) {
        int row = base + r0 + r;
        if (row < n_total) {
            float inv = 1.0f / fmaxf(sqrtf(s[r]), 1e-12f);
            #pragma unroll
            for (int c = 0; c < 4; c++) {
                if (writeE) g_E[row * D + cols[c]] = ev[r][c];
                __stcs(&out[row * 4 * D + out_col + cols[c]], ev[r][c] * inv);
            }
        }
    }
}

extern "C" void kernel_launch(void* const* d_in, const int* in_sizes, int n_in,
                              void* d_out, int out_size) {
    const float* user = (const float*)d_in[0];
    const float* item = (const float*)d_in[1];
    const int*   erow = (const int*)d_in[2];
    const int*   ecol = (const int*)d_in[3];
    const float* eval = (const float*)d_in[4];
    const float* Wf   = (const float*)d_in[5];
    const float* bf   = (const float*)d_in[6];
    const float* Wb   = (const float*)d_in[7];
    const float* bb   = (const float*)d_in[8];
    float* out = (float*)d_out;

    int n_user = in_sizes[0] / D;
    int n_item = in_sizes[1] / D;
    int N  = n_user + n_item;
    int nE = in_sizes[2];

    const int smem_bytes = 4 * 64 * 68 * 4;  // 69632 B dynamic smem
    cudaFuncSetAttribute(fused_kernel, cudaFuncAttributeMaxDynamicSharedMemorySize, smem_bytes);

    init_kernel<<<(N * 16 + 255) / 256, 256>>>(user, item, out, n_user, N);

    for (int i = 0; i < 3; i++) {
        scatter_kernel<<<(nE * 16 + 255) / 256, 256>>>(erow, ecol, eval, nE);
        fused_kernel<<<(N + RPB - 1) / RPB, TPB, smem_bytes>>>(
            Wf + i * 4096, bf + i * 64, Wb + i * 4096, bb + i * 64,
            out, (i + 1) * 64, N, (i < 2) ? 1 : 0);
    }
}

// round 8
// speedup vs baseline: 1.1439x; 1.1439x over previous
#include <cuda_runtime.h>
#include <cstdint>

#define D 64
#define NMAX 150016          // max total nodes (100000 + 50000, padded)
#define RPB 64               // rows per block in fused kernel
#define TPB 512              // threads per block in fused kernel (16 warps)

// Scratch: static device globals (module-load allocation, allowed by harness rules)
__device__ float g_E[NMAX * D];     // current layer embeddings (unnormalized)
__device__ float g_agg[NMAX * D];   // edge aggregation accumulator

__device__ __forceinline__ float lrelu(float x) {
    return x > 0.0f ? x : 0.01f * x;
}

// Packed f32x2 helpers (sm_100+ base feature, not 'a'-gated)
#define FMA2(d, a, b) \
    asm("fma.rn.f32x2 %0, %1, %2, %0;" : "+l"(d) : "l"(a), "l"(b))
__device__ __forceinline__ unsigned long long pk2(float x, float y) {
    unsigned long long v;
    asm("mov.b64 %0, {%1, %2};" : "=l"(v) : "f"(x), "f"(y));
    return v;
}
__device__ __forceinline__ float2 upk2(unsigned long long v) {
    float2 r;
    asm("mov.b64 {%0, %1}, %2;" : "=f"(r.x), "=f"(r.y) : "l"(v));
    return r;
}

// E0 = concat(user, item); write raw E0 into out[:, 0:64]; zero g_agg
__global__ void init_kernel(const float* __restrict__ user, const float* __restrict__ item,
                            float* __restrict__ out, int n_user, int n_total) {
    int t = blockIdx.x * blockDim.x + threadIdx.x;
    if (t >= n_total * (D / 4)) return;
    int row = t >> 4;
    int c = (t & 15) * 4;
    float4 v;
    if (row < n_user) v = *(const float4*)&user[row * D + c];
    else              v = *(const float4*)&item[(row - n_user) * D + c];
    *(float4*)&g_E[row * D + c] = v;
    *(float4*)&g_agg[row * D + c] = make_float4(0.f, 0.f, 0.f, 0.f);
    __stcs((float4*)&out[row * 4 * D + c], v);
}

// agg[row] += val * E[col] per edge. 16 threads (half-warp) per edge, one float4 each.
__global__ void scatter_kernel(const int* __restrict__ erow, const int* __restrict__ ecol,
                               const float* __restrict__ eval, int nE) {
    int t = blockIdx.x * blockDim.x + threadIdx.x;
    int e = t >> 4;
    int lane = threadIdx.x & 31;
    int src = lane & 16;                 // leader lane of this half-warp
    int r = 0, cl = 0; float v = 0.f;
    if ((lane & 15) == 0 && e < nE) { r = erow[e]; cl = ecol[e]; v = eval[e]; }
    r  = __shfl_sync(0xffffffffu, r,  src);
    cl = __shfl_sync(0xffffffffu, cl, src);
    v  = __shfl_sync(0xffffffffu, v,  src);
    if (e >= nE) return;
    int c = (t & 15) * 4;
    float4 x = *(const float4*)&g_E[cl * D + c];
    atomicAdd((float4*)&g_agg[r * D + c], make_float4(v * x.x, v * x.y, v * x.z, v * x.w));
}

// Per row n:
//   f = agg[n] + E[n] (+I folded); agg zeroed in place (if zeroAgg)
//   t = lrelu(f @ Wf^T + bf); u = lrelu((E[n]*f) @ Wb^T + bb)
//   Enew = t + u -> g_E (if writeE); out[n, out_col:+64] = Enew/||Enew||
// Block: 64 rows, 512 threads. Warp w: rows w*4..w*4+3. Lane: cols (lane, lane+32).
// f32x2 packed math: accumulators hold row-pairs; weights stored duplicated {w,w} in smem.
#define WSTRIDE 132          // floats per weight row: 4-bank stagger, conflict-free LDS.128
__global__ void __launch_bounds__(TPB, 2)
fused_kernel(const float* __restrict__ Wf, const float* __restrict__ bfv,
             const float* __restrict__ Wb, const float* __restrict__ bbv,
             float* __restrict__ out, int out_col, int n_total, int writeE, int zeroAgg) {
    extern __shared__ float sm[];
    float* wdf = sm;                    // [j][2k..2k+1] = {Wf[j][k], Wf[j][k]}
    float* wdb = wdf + 64 * WSTRIDE;
    float* fs  = wdb + 64 * WSTRIDE;    // [k][r], stride 68 -> broadcast LDS.128
    float* efs = fs + 64 * 68;

    int tid  = threadIdx.x;
    int lane = tid & 31;
    int w    = tid >> 5;                // 0..15
    int base = blockIdx.x * RPB;

    // Stage weights duplicated (global [j][k] row-major)
    for (int idx = tid; idx < 4096; idx += TPB) {
        int j = idx >> 6, k = idx & 63;
        float a = Wf[idx], b = Wb[idx];
        *(float2*)&wdf[j * WSTRIDE + 2 * k] = make_float2(a, a);
        *(float2*)&wdb[j * WSTRIDE + 2 * k] = make_float2(b, b);
    }
    // Stage rows: f = agg+E, ef = E*f; optionally zero agg in place
    for (int idx = tid; idx < 4096; idx += TPB) {
        int r = idx >> 6, k = idx & 63;
        int row = base + r;
        float e = 0.f, a = 0.f;
        if (row < n_total) {
            e = g_E[row * D + k];
            a = g_agg[row * D + k];
            if (zeroAgg) g_agg[row * D + k] = 0.f;
        }
        float f = a + e;
        fs[k * 68 + r]  = f;
        efs[k * 68 + r] = e * f;
    }
    __syncthreads();

    int j0 = lane, j1 = lane + 32;
    int r0 = w * 4;

    // acc[c][p]: column c (0->j0, 1->j1), row-pair p (rows r0+2p, r0+2p+1)
    unsigned long long af[2][2], ab[2][2];
    {
        unsigned long long b00 = pk2(bfv[j0], bfv[j0]);
        unsigned long long b01 = pk2(bfv[j1], bfv[j1]);
        unsigned long long b10 = pk2(bbv[j0], bbv[j0]);
        unsigned long long b11 = pk2(bbv[j1], bbv[j1]);
        af[0][0] = b00; af[0][1] = b00;
        af[1][0] = b01; af[1][1] = b01;
        ab[0][0] = b10; ab[0][1] = b10;
        ab[1][0] = b11; ab[1][1] = b11;
    }

    #pragma unroll
    for (int k = 0; k < 64; k += 2) {
        // duplicated weight pairs for k and k+1 (16B loads, conflict-free)
        ulonglong2 qf0 = *(const ulonglong2*)&wdf[j0 * WSTRIDE + 2 * k];
        ulonglong2 qf1 = *(const ulonglong2*)&wdf[j1 * WSTRIDE + 2 * k];
        ulonglong2 qb0 = *(const ulonglong2*)&wdb[j0 * WSTRIDE + 2 * k];
        ulonglong2 qb1 = *(const ulonglong2*)&wdb[j1 * WSTRIDE + 2 * k];
        #pragma unroll
        for (int kk = 0; kk < 2; kk++) {
            // data row-pairs: .x = rows (r0, r0+1), .y = rows (r0+2, r0+3); broadcast
            ulonglong2 f = *(const ulonglong2*)&fs[(k + kk) * 68 + r0];
            ulonglong2 e = *(const ulonglong2*)&efs[(k + kk) * 68 + r0];
            unsigned long long wf0 = kk ? qf0.y : qf0.x;
            unsigned long long wf1 = kk ? qf1.y : qf1.x;
            unsigned long long wb0 = kk ? qb0.y : qb0.x;
            unsigned long long wb1 = kk ? qb1.y : qb1.x;
            FMA2(af[0][0], f.x, wf0);  FMA2(af[0][1], f.y, wf0);
            FMA2(af[1][0], f.x, wf1);  FMA2(af[1][1], f.y, wf1);
            FMA2(ab[0][0], e.x, wb0);  FMA2(ab[0][1], e.y, wb0);
            FMA2(ab[1][0], e.x, wb1);  FMA2(ab[1][1], e.y, wb1);
        }
    }

    // Unpack: fa[r][c], fb[r][c] for rows r0..r0+3, cols {j0, j1}
    float fa[4][2], fb[4][2];
    #pragma unroll
    for (int c = 0; c < 2; c++) {
        #pragma unroll
        for (int p = 0; p < 2; p++) {
            float2 t = upk2(af[c][p]);
            fa[2 * p][c] = t.x; fa[2 * p + 1][c] = t.y;
            float2 u = upk2(ab[c][p]);
            fb[2 * p][c] = u.x; fb[2 * p + 1][c] = u.y;
        }
    }

    // Epilogue: leaky-relu, sum, row-norm (warp covers all 64 cols of its 4 rows)
    #pragma unroll
    for (int r = 0; r < 4; r++) {
        int row = base + r0 + r;
        float e0 = lrelu(fa[r][0]) + lrelu(fb[r][0]);
        float e1 = lrelu(fa[r][1]) + lrelu(fb[r][1]);
        float s = e0 * e0 + e1 * e1;
        #pragma unroll
        for (int o = 16; o; o >>= 1) s += __shfl_xor_sync(0xffffffffu, s, o);
        float inv = 1.0f / fmaxf(sqrtf(s), 1e-12f);
        if (row < n_total) {
            if (writeE) {
                g_E[row * D + j0] = e0;
                g_E[row * D + j1] = e1;
            }
            __stcs(&out[row * 4 * D + out_col + j0], e0 * inv);
            __stcs(&out[row * 4 * D + out_col + j1], e1 * inv);
        }
    }
}

extern "C" void kernel_launch(void* const* d_in, const int* in_sizes, int n_in,
                              void* d_out, int out_size) {
    const float* user = (const float*)d_in[0];
    const float* item = (const float*)d_in[1];
    const int*   erow = (const int*)d_in[2];
    const int*   ecol = (const int*)d_in[3];
    const float* eval = (const float*)d_in[4];
    const float* Wf   = (const float*)d_in[5];
    const float* bf   = (const float*)d_in[6];
    const float* Wb   = (const float*)d_in[7];
    const float* bb   = (const float*)d_in[8];
    float* out = (float*)d_out;

    int n_user = in_sizes[0] / D;
    int n_item = in_sizes[1] / D;
    int N  = n_user + n_item;
    int nE = in_sizes[2];

    // smem: 2 * 64*132 (dup weights) + 2 * 64*68 (fs/efs) floats = 102400 bytes
    const int smem_bytes = (2 * 64 * WSTRIDE + 2 * 64 * 68) * 4;
    cudaFuncSetAttribute(fused_kernel, cudaFuncAttributeMaxDynamicSharedMemorySize, smem_bytes);

    init_kernel<<<(N * 16 + 255) / 256, 256>>>(user, item, out, n_user, N);

    for (int i = 0; i < 3; i++) {
        scatter_kernel<<<(nE * 16 + 255) / 256, 256>>>(erow, ecol, eval, nE);
        fused_kernel<<<(N + RPB - 1) / RPB, TPB, smem_bytes>>>(
            Wf + i * 4096, bf + i * 64, Wb + i * 4096, bb + i * 64,
            out, (i + 1) * 64, N, (i < 2) ? 1 : 0, (i < 2) ? 1 : 0);
    }
}

// round 9
// speedup vs baseline: 1.2521x; 1.0946x over previous
#include <cuda_runtime.h>

#define D 64
#define NMAX 150016          // max total nodes (100000 + 50000, padded)
#define RPB 128              // rows per block in fused kernel
#define TPB 1024             // threads per block in fused kernel (32 warps)
#define RSTRIDE 132          // row stride (floats) of fs/efs: 128 rows + 4 pad

// Scratch: static device globals (module-load allocation, allowed by harness rules)
__device__ float g_E[NMAX * D];     // current layer embeddings (unnormalized)
__device__ float g_agg[NMAX * D];   // edge aggregation accumulator

__device__ __forceinline__ float lrelu(float x) {
    return x > 0.0f ? x : 0.01f * x;
}

// E0 = concat(user, item); write raw E0 into out[:, 0:64]; zero g_agg
__global__ void init_kernel(const float* __restrict__ user, const float* __restrict__ item,
                            float* __restrict__ out, int n_user, int n_total) {
    int t = blockIdx.x * blockDim.x + threadIdx.x;
    if (t >= n_total * (D / 4)) return;
    int row = t >> 4;
    int c = (t & 15) * 4;
    float4 v;
    if (row < n_user) v = *(const float4*)&user[row * D + c];
    else              v = *(const float4*)&item[(row - n_user) * D + c];
    *(float4*)&g_E[row * D + c] = v;
    *(float4*)&g_agg[row * D + c] = make_float4(0.f, 0.f, 0.f, 0.f);
    __stcs((float4*)&out[row * 4 * D + c], v);
}

// agg[row] += val * E[col] per edge. 16 threads (half-warp) per edge, one float4 each.
__global__ void scatter_kernel(const int* __restrict__ erow, const int* __restrict__ ecol,
                               const float* __restrict__ eval, int nE) {
    int t = blockIdx.x * blockDim.x + threadIdx.x;
    int e = t >> 4;
    int lane = threadIdx.x & 31;
    int src = lane & 16;                 // leader lane of this half-warp
    int r = 0, cl = 0; float v = 0.f;
    if ((lane & 15) == 0 && e < nE) { r = erow[e]; cl = ecol[e]; v = eval[e]; }
    r  = __shfl_sync(0xffffffffu, r,  src);
    cl = __shfl_sync(0xffffffffu, cl, src);
    v  = __shfl_sync(0xffffffffu, v,  src);
    if (e >= nE) return;
    int c = (t & 15) * 4;
    float4 x = *(const float4*)&g_E[cl * D + c];
    atomicAdd((float4*)&g_agg[r * D + c], make_float4(v * x.x, v * x.y, v * x.z, v * x.w));
}

// Per row n:
//   f = agg[n] + E[n] (+I folded); agg zeroed in place (if zeroAgg)
//   t = lrelu(f @ Wf^T + bf); u = lrelu((E[n]*f) @ Wb^T + bb)
//   Enew = t + u -> g_E (if writeE); out[n, out_col:+64] = Enew/||Enew||
// Block: 128 rows, 1024 threads (32 warps). Warp w: rows 4w..4w+3.
// Lane: cols (lane, lane+32). Identical per-thread microkernel to the proven R1 kernel.
__global__ void fused_kernel(const float* __restrict__ Wf, const float* __restrict__ bfv,
                             const float* __restrict__ Wb, const float* __restrict__ bbv,
                             float* __restrict__ out, int out_col, int n_total,
                             int writeE, int zeroAgg) {
    extern __shared__ float sm[];
    float* Wfs = sm;               // [j][k] stride 68 -> conflict-free float4 reads along k
    float* Wbs = Wfs + 64 * 68;
    float* fs  = Wbs + 64 * 68;    // [k][r] stride 132 -> broadcast LDS.128
    float* efs = fs + 64 * RSTRIDE;

    int tid  = threadIdx.x;
    int lane = tid & 31;
    int w    = tid >> 5;           // 0..31
    int base = blockIdx.x * RPB;

    // Stage weights (global [j][k] row-major; out[n,j] = sum_k x[n,k]*W[j,k])
    for (int idx = tid; idx < 4096; idx += TPB) {
        int j = idx >> 6, k = idx & 63;
        Wfs[j * 68 + k] = Wf[idx];
        Wbs[j * 68 + k] = Wb[idx];
    }
    // Stage rows: f = agg+E, ef = E*f; zero agg in place (replaces zero_kernel)
    for (int idx = tid; idx < RPB * D; idx += TPB) {
        int r = idx >> 6, k = idx & 63;
        int row = base + r;
        float e = 0.f, a = 0.f;
        if (row < n_total) {
            e = g_E[row * D + k];
            a = g_agg[row * D + k];
            if (zeroAgg) g_agg[row * D + k] = 0.f;
        }
        float f = a + e;
        fs[k * RSTRIDE + r]  = f;
        efs[k * RSTRIDE + r] = e * f;
    }
    __syncthreads();

    int j0 = lane, j1 = lane + 32;
    int r0 = w * 4;
    float af[4][2], ab[4][2];
    {
        float bf0 = bfv[j0], bf1 = bfv[j1], bb0 = bbv[j0], bb1 = bbv[j1];
        #pragma unroll
        for (int r = 0; r < 4; r++) {
            af[r][0] = bf0; af[r][1] = bf1;
            ab[r][0] = bb0; ab[r][1] = bb1;
        }
    }

    #pragma unroll
    for (int k = 0; k < 64; k += 4) {
        float4 wf0 = *(float4*)&Wfs[j0 * 68 + k];
        float4 wf1 = *(float4*)&Wfs[j1 * 68 + k];
        float4 wb0 = *(float4*)&Wbs[j0 * 68 + k];
        float4 wb1 = *(float4*)&Wbs[j1 * 68 + k];
        #pragma unroll
        for (int kk = 0; kk < 4; kk++) {
            float4 f  = *(float4*)&fs[(k + kk) * RSTRIDE + r0];
            float4 ef = *(float4*)&efs[(k + kk) * RSTRIDE + r0];
            float a = (&wf0.x)[kk], b = (&wf1.x)[kk];
            float c = (&wb0.x)[kk], d = (&wb1.x)[kk];
            af[0][0] += f.x * a;  af[0][1] += f.x * b;
            af[1][0] += f.y * a;  af[1][1] += f.y * b;
            af[2][0] += f.z * a;  af[2][1] += f.z * b;
            af[3][0] += f.w * a;  af[3][1] += f.w * b;
            ab[0][0] += ef.x * c; ab[0][1] += ef.x * d;
            ab[1][0] += ef.y * c; ab[1][1] += ef.y * d;
            ab[2][0] += ef.z * c; ab[2][1] += ef.z * d;
            ab[3][0] += ef.w * c; ab[3][1] += ef.w * d;
        }
    }

    // Epilogue: leaky-relu, sum, row-norm (warp covers all 64 cols of each of its 4 rows)
    #pragma unroll
    for (int r = 0; r < 4; r++) {
        int row = base + r0 + r;
        float e0 = lrelu(af[r][0]) + lrelu(ab[r][0]);
        float e1 = lrelu(af[r][1]) + lrelu(ab[r][1]);
        float s = e0 * e0 + e1 * e1;
        #pragma unroll
        for (int o = 16; o; o >>= 1) s += __shfl_xor_sync(0xffffffffu, s, o);
        float inv = 1.0f / fmaxf(sqrtf(s), 1e-12f);
        if (row < n_total) {
            if (writeE) {
                g_E[row * D + j0] = e0;
                g_E[row * D + j1] = e1;
            }
            __stcs(&out[row * 4 * D + out_col + j0], e0 * inv);
            __stcs(&out[row * 4 * D + out_col + j1], e1 * inv);
        }
    }
}

extern "C" void kernel_launch(void* const* d_in, const int* in_sizes, int n_in,
                              void* d_out, int out_size) {
    const float* user = (const float*)d_in[0];
    const float* item = (const float*)d_in[1];
    const int*   erow = (const int*)d_in[2];
    const int*   ecol = (const int*)d_in[3];
    const float* eval = (const float*)d_in[4];
    const float* Wf   = (const float*)d_in[5];
    const float* bf   = (const float*)d_in[6];
    const float* Wb   = (const float*)d_in[7];
    const float* bb   = (const float*)d_in[8];
    float* out = (float*)d_out;

    int n_user = in_sizes[0] / D;
    int n_item = in_sizes[1] / D;
    int N  = n_user + n_item;
    int nE = in_sizes[2];

    // smem: 2*64*68 (weights) + 2*64*132 (fs/efs) floats = 102400 bytes
    const int smem_bytes = (2 * 64 * 68 + 2 * 64 * RSTRIDE) * 4;
    cudaFuncSetAttribute(fused_kernel, cudaFuncAttributeMaxDynamicSharedMemorySize, smem_bytes);

    init_kernel<<<(N * 16 + 255) / 256, 256>>>(user, item, out, n_user, N);

    for (int i = 0; i < 3; i++) {
        scatter_kernel<<<(nE * 16 + 255) / 256, 256>>>(erow, ecol, eval, nE);
        fused_kernel<<<(N + RPB - 1) / RPB, TPB, smem_bytes>>>(
            Wf + i * 4096, bf + i * 64, Wb + i * 4096, bb + i * 64,
            out, (i + 1) * 64, N, (i < 2) ? 1 : 0, (i < 2) ? 1 : 0);
    }
}

// round 12
// speedup vs baseline: 1.3006x; 1.0387x over previous
#include <cuda_runtime.h>

#define D 64
#define NMAX 150016          // max total nodes (100000 + 50000, padded)
#define RPB 64               // rows per block in fused kernel
#define TPB 512              // threads per block in fused kernel (16 warps)
#define WSTR 66              // weight smem row stride (floats): LDS.64 conflict-min
#define FSTR 68              // data smem row stride (floats)

// Scratch: static device globals (module-load allocation, allowed by harness rules)
__device__ float g_E[NMAX * D];     // current layer embeddings (unnormalized)
__device__ float g_agg[NMAX * D];   // edge aggregation accumulator

__device__ __forceinline__ float lrelu(float x) {
    return x > 0.0f ? x : 0.01f * x;
}

// E0 = concat(user, item); write raw E0 into out[:, 0:64]; zero g_agg
__global__ void init_kernel(const float* __restrict__ user, const float* __restrict__ item,
                            float* __restrict__ out, int n_user, int n_total) {
    int t = blockIdx.x * blockDim.x + threadIdx.x;
    if (t >= n_total * (D / 4)) return;
    int row = t >> 4;
    int c = (t & 15) * 4;
    float4 v;
    if (row < n_user) v = *(const float4*)&user[row * D + c];
    else              v = *(const float4*)&item[(row - n_user) * D + c];
    *(float4*)&g_E[row * D + c] = v;
    *(float4*)&g_agg[row * D + c] = make_float4(0.f, 0.f, 0.f, 0.f);
    __stcs((float4*)&out[row * 4 * D + c], v);
}

// agg[row] += val * E[col] per edge. 16 threads (half-warp) per edge, one float4 each.
__global__ void scatter_kernel(const int* __restrict__ erow, const int* __restrict__ ecol,
                               const float* __restrict__ eval, int nE) {
    int t = blockIdx.x * blockDim.x + threadIdx.x;
    int e = t >> 4;
    int lane = threadIdx.x & 31;
    int src = lane & 16;                 // leader lane of this half-warp
    int r = 0, cl = 0; float v = 0.f;
    if ((lane & 15) == 0 && e < nE) { r = erow[e]; cl = ecol[e]; v = eval[e]; }
    r  = __shfl_sync(0xffffffffu, r,  src);
    cl = __shfl_sync(0xffffffffu, cl, src);
    v  = __shfl_sync(0xffffffffu, v,  src);
    if (e >= nE) return;
    int c = (t & 15) * 4;
    float4 x = *(const float4*)&g_E[cl * D + c];
    atomicAdd((float4*)&g_agg[r * D + c], make_float4(v * x.x, v * x.y, v * x.z, v * x.w));
}

// Per row n:
//   f = agg[n] + E[n] (+I folded); agg zeroed in place (if zeroAgg)
//   t = lrelu(f @ Wf^T + bf); u = lrelu((E[n]*f) @ Wb^T + bb)
//   Enew = t + u -> g_E (if writeE); out[n, out_col:+64] = Enew/||Enew||
// Block: 64 rows, 512 threads, 3 blocks/SM target (register-capped via launch_bounds).
// Warp w: rows 4w..4w+3. Lane: cols (lane, lane+32). k-step 2, LDS.64 weights.
__global__ void __launch_bounds__(TPB, 3)
fused_kernel(const float* __restrict__ Wf, const float* __restrict__ bfv,
             const float* __restrict__ Wb, const float* __restrict__ bbv,
             float* __restrict__ out, int out_col, int n_total,
             int writeE, int zeroAgg) {
    extern __shared__ float sm[];
    float* Wfs = sm;                 // [j][k] stride 66
    float* Wbs = Wfs + 64 * WSTR;
    float* fs  = Wbs + 64 * WSTR;    // [k][r] stride 68 -> broadcast LDS.128
    float* efs = fs + 64 * FSTR;

    int tid  = threadIdx.x;
    int lane = tid & 31;
    int w    = tid >> 5;             // 0..15
    int base = blockIdx.x * RPB;

    // Stage weights (global [j][k] row-major; out[n,j] = sum_k x[n,k]*W[j,k])
    for (int idx = tid; idx < 4096; idx += TPB) {
        int j = idx >> 6, k = idx & 63;
        Wfs[j * WSTR + k] = Wf[idx];
        Wbs[j * WSTR + k] = Wb[idx];
    }
    // Stage rows: f = agg+E, ef = E*f; zero agg in place (replaces zero_kernel)
    for (int idx = tid; idx < RPB * D; idx += TPB) {
        int r = idx >> 6, k = idx & 63;
        int row = base + r;
        float e = 0.f, a = 0.f;
        if (row < n_total) {
            e = g_E[row * D + k];
            a = g_agg[row * D + k];
            if (zeroAgg) g_agg[row * D + k] = 0.f;
        }
        float f = a + e;
        fs[k * FSTR + r]  = f;
        efs[k * FSTR + r] = e * f;
    }
    __syncthreads();

    int j0 = lane, j1 = lane + 32;
    int r0 = w * 4;
    float af[4][2], ab[4][2];
    {
        float bf0 = bfv[j0], bf1 = bfv[j1], bb0 = bbv[j0], bb1 = bbv[j1];
        #pragma unroll
        for (int r = 0; r < 4; r++) {
            af[r][0] = bf0; af[r][1] = bf1;
            ab[r][0] = bb0; ab[r][1] = bb1;
        }
    }

    #pragma unroll
    for (int k = 0; k < 64; k += 2) {
        float2 wf0 = *(const float2*)&Wfs[j0 * WSTR + k];
        float2 wf1 = *(const float2*)&Wfs[j1 * WSTR + k];
        float2 wb0 = *(const float2*)&Wbs[j0 * WSTR + k];
        float2 wb1 = *(const float2*)&Wbs[j1 * WSTR + k];
        #pragma unroll
        for (int kk = 0; kk < 2; kk++) {
            float4 f  = *(const float4*)&fs[(k + kk) * FSTR + r0];
            float4 ef = *(const float4*)&efs[(k + kk) * FSTR + r0];
            float a = kk ? wf0.y : wf0.x;
            float b = kk ? wf1.y : wf1.x;
            float c = kk ? wb0.y : wb0.x;
            float d = kk ? wb1.y : wb1.x;
            af[0][0] += f.x * a;  af[0][1] += f.x * b;
            af[1][0] += f.y * a;  af[1][1] += f.y * b;
            af[2][0] += f.z * a;  af[2][1] += f.z * b;
            af[3][0] += f.w * a;  af[3][1] += f.w * b;
            ab[0][0] += ef.x * c; ab[0][1] += ef.x * d;
            ab[1][0] += ef.y * c; ab[1][1] += ef.y * d;
            ab[2][0] += ef.z * c; ab[2][1] += ef.z * d;
            ab[3][0] += ef.w * c; ab[3][1] += ef.w * d;
        }
    }

    // Epilogue: leaky-relu, sum, row-norm (warp covers all 64 cols of each of its 4 rows)
    #pragma unroll
    for (int r = 0; r < 4; r++) {
        int row = base + r0 + r;
        float e0 = lrelu(af[r][0]) + lrelu(ab[r][0]);
        float e1 = lrelu(af[r][1]) + lrelu(ab[r][1]);
        float s = e0 * e0 + e1 * e1;
        #pragma unroll
        for (int o = 16; o; o >>= 1) s += __shfl_xor_sync(0xffffffffu, s, o);
        float inv = 1.0f / fmaxf(sqrtf(s), 1e-12f);
        if (row < n_total) {
            if (writeE) {
                g_E[row * D + j0] = e0;
                g_E[row * D + j1] = e1;
            }
            __stcs(&out[row * 4 * D + out_col + j0], e0 * inv);
            __stcs(&out[row * 4 * D + out_col + j1], e1 * inv);
        }
    }
}

extern "C" void kernel_launch(void* const* d_in, const int* in_sizes, int n_in,
                              void* d_out, int out_size) {
    const float* user = (const float*)d_in[0];
    const float* item = (const float*)d_in[1];
    const int*   erow = (const int*)d_in[2];
    const int*   ecol = (const int*)d_in[3];
    const float* eval = (const float*)d_in[4];
    const float* Wf   = (const float*)d_in[5];
    const float* bf   = (const float*)d_in[6];
    const float* Wb   = (const float*)d_in[7];
    const float* bb   = (const float*)d_in[8];
    float* out = (float*)d_out;

    int n_user = in_sizes[0] / D;
    int n_item = in_sizes[1] / D;
    int N  = n_user + n_item;
    int nE = in_sizes[2];

    // smem: 2*64*66 (weights) + 2*64*68 (fs/efs) floats = 68608 bytes -> 3 blocks/SM
    const int smem_bytes = (2 * 64 * WSTR + 2 * 64 * FSTR) * 4;
    cudaFuncSetAttribute(fused_kernel, cudaFuncAttributeMaxDynamicSharedMemorySize, smem_bytes);

    init_kernel<<<(N * 16 + 255) / 256, 256>>>(user, item, out, n_user, N);

    for (int i = 0; i < 3; i++) {
        scatter_kernel<<<(nE * 16 + 255) / 256, 256>>>(erow, ecol, eval, nE);
        fused_kernel<<<(N + RPB - 1) / RPB, TPB, smem_bytes>>>(
            Wf + i * 4096, bf + i * 64, Wb + i * 4096, bb + i * 64,
            out, (i + 1) * 64, N, (i < 2) ? 1 : 0, (i < 2) ? 1 : 0);
    }
}

// round 17
// speedup vs baseline: 1.8761x; 1.4425x over previous
#include <cuda_runtime.h>

#define D 64
#define NMAX 150016          // max total nodes (100000 + 50000, padded)
#define RPB 64               // rows per block in fused kernel
#define TPB 512              // threads per block in fused kernel (16 warps)
#define WSTR 66              // weight smem row stride (floats): LDS.64 conflict-min
#define FSTR 68              // data smem row stride (floats)

// Scratch: static device globals (module-load allocation, allowed by harness rules)
__device__ float g_E[NMAX * D];     // current layer embeddings (unnormalized)
__device__ float g_agg[NMAX * D];   // edge aggregation accumulator

__device__ __forceinline__ float lrelu(float x) {
    return x > 0.0f ? x : 0.01f * x;
}

// E0 = concat(user, item); write raw E0 into out[:, 0:64]
__global__ void initE_kernel(const float* __restrict__ user, const float* __restrict__ item,
                             float* __restrict__ out, int n_user, int n_total) {
    int t = blockIdx.x * blockDim.x + threadIdx.x;
    if (t >= n_total * (D / 4)) return;
    int row = t >> 4;
    int c = (t & 15) * 4;
    float4 v;
    if (row < n_user) v = *(const float4*)&user[row * D + c];
    else              v = *(const float4*)&item[(row - n_user) * D + c];
    *(float4*)&g_E[row * D + c] = v;
    __stcs((float4*)&out[row * 4 * D + c], v);
}

__global__ void zero_agg_kernel(int n_total) {
    int t = blockIdx.x * blockDim.x + threadIdx.x;
    if (t < n_total * (D / 4))
        ((float4*)g_agg)[t] = make_float4(0.f, 0.f, 0.f, 0.f);
}

// agg[row] += val * E[col] per edge. 16 threads (half-warp) per edge, one float4 each.
__global__ void scatter_kernel(const int* __restrict__ erow, const int* __restrict__ ecol,
                               const float* __restrict__ eval, int nE) {
    int t = blockIdx.x * blockDim.x + threadIdx.x;
    int e = t >> 4;
    int lane = threadIdx.x & 31;
    int src = lane & 16;                 // leader lane of this half-warp
    int r = 0, cl = 0; float v = 0.f;
    if ((lane & 15) == 0 && e < nE) { r = erow[e]; cl = ecol[e]; v = eval[e]; }
    r  = __shfl_sync(0xffffffffu, r,  src);
    cl = __shfl_sync(0xffffffffu, cl, src);
    v  = __shfl_sync(0xffffffffu, v,  src);
    if (e >= nE) return;
    int c = (t & 15) * 4;
    float4 x = *(const float4*)&g_E[cl * D + c];
    atomicAdd((float4*)&g_agg[r * D + c], make_float4(v * x.x, v * x.y, v * x.z, v * x.w));
}

// Per row n:
//   f = agg[n] + E[n] (+I folded); agg zeroed in place (if zeroAgg)
//   t = lrelu(f @ Wf^T + bf); u = lrelu((E[n]*f) @ Wb^T + bb)
//   Enew = t + u -> g_E (if writeE); out[n, out_col:+64] = Enew/||Enew||
// Block: 64 rows, 512 threads, 3 blocks/SM target. Warp w: rows 4w..4w+3.
// Lane: cols (lane, lane+32). k-step 2, LDS.64 weights. Bias added in epilogue.
__global__ void __launch_bounds__(TPB, 3)
fused_kernel(const float* __restrict__ Wf, const float* __restrict__ bfv,
             const float* __restrict__ Wb, const float* __restrict__ bbv,
             float* __restrict__ out, int out_col, int n_total,
             int writeE, int zeroAgg) {
    extern __shared__ float sm[];
    float* Wfs = sm;                 // [j][k] stride 66
    float* Wbs = Wfs + 64 * WSTR;
    float* fs  = Wbs + 64 * WSTR;    // [k][r] stride 68 -> broadcast LDS.128
    float* efs = fs + 64 * FSTR;

    int tid  = threadIdx.x;
    int lane = tid & 31;
    int w    = tid >> 5;             // 0..15
    int base = blockIdx.x * RPB;

    // Stage weights, vectorized LDG.128 (global [j][k] row-major)
    for (int idx = tid; idx < 1024; idx += TPB) {
        int j = idx >> 4, k4 = (idx & 15) * 4;
        float4 wf = *(const float4*)&Wf[j * D + k4];
        float4 wb = *(const float4*)&Wb[j * D + k4];
        Wfs[j * WSTR + k4 + 0] = wf.x;  Wfs[j * WSTR + k4 + 1] = wf.y;
        Wfs[j * WSTR + k4 + 2] = wf.z;  Wfs[j * WSTR + k4 + 3] = wf.w;
        Wbs[j * WSTR + k4 + 0] = wb.x;  Wbs[j * WSTR + k4 + 1] = wb.y;
        Wbs[j * WSTR + k4 + 2] = wb.z;  Wbs[j * WSTR + k4 + 3] = wb.w;
    }
    // Stage rows vectorized: f = agg+E, ef = E*f; zero agg in place
    for (int idx = tid; idx < RPB * D / 4; idx += TPB) {
        int r = idx >> 4, k4 = (idx & 15) * 4;
        int row = base + r;
        float4 e = make_float4(0.f, 0.f, 0.f, 0.f);
        float4 a = e;
        if (row < n_total) {
            e = *(const float4*)&g_E[row * D + k4];
            a = *(const float4*)&g_agg[row * D + k4];
            if (zeroAgg) *(float4*)&g_agg[row * D + k4] = make_float4(0.f, 0.f, 0.f, 0.f);
        }
        #pragma unroll
        for (int c = 0; c < 4; c++) {
            float ev = (&e.x)[c];
            float f  = (&a.x)[c] + ev;
            fs[(k4 + c) * FSTR + r]  = f;
            efs[(k4 + c) * FSTR + r] = ev * f;
        }
    }
    __syncthreads();

    int j0 = lane, j1 = lane + 32;
    int r0 = w * 4;
    float af[4][2] = {}, ab[4][2] = {};

    #pragma unroll
    for (int k = 0; k < 64; k += 2) {
        float2 wf0 = *(const float2*)&Wfs[j0 * WSTR + k];
        float2 wf1 = *(const float2*)&Wfs[j1 * WSTR + k];
        float2 wb0 = *(const float2*)&Wbs[j0 * WSTR + k];
        float2 wb1 = *(const float2*)&Wbs[j1 * WSTR + k];
        #pragma unroll
        for (int kk = 0; kk < 2; kk++) {
            float4 f  = *(const float4*)&fs[(k + kk) * FSTR + r0];
            float4 ef = *(const float4*)&efs[(k + kk) * FSTR + r0];
            float a = kk ? wf0.y : wf0.x;
            float b = kk ? wf1.y : wf1.x;
            float c = kk ? wb0.y : wb0.x;
            float d = kk ? wb1.y : wb1.x;
            af[0][0] += f.x * a;  af[0][1] += f.x * b;
            af[1][0] += f.y * a;  af[1][1] += f.y * b;
            af[2][0] += f.z * a;  af[2][1] += f.z * b;
            af[3][0] += f.w * a;  af[3][1] += f.w * b;
            ab[0][0] += ef.x * c; ab[0][1] += ef.x * d;
            ab[1][0] += ef.y * c; ab[1][1] += ef.y * d;
            ab[2][0] += ef.z * c; ab[2][1] += ef.z * d;
            ab[3][0] += ef.w * c; ab[3][1] += ef.w * d;
        }
    }

    // Epilogue: bias, leaky-relu, sum, row-norm
    float bf0 = bfv[j0], bf1 = bfv[j1], bb0 = bbv[j0], bb1 = bbv[j1];
    #pragma unroll
    for (int r = 0; r < 4; r++) {
        int row = base + r0 + r;
        float e0 = lrelu(af[r][0] + bf0) + lrelu(ab[r][0] + bb0);
        float e1 = lrelu(af[r][1] + bf1) + lrelu(ab[r][1] + bb1);
        float s = e0 * e0 + e1 * e1;
        #pragma unroll
        for (int o = 16; o; o >>= 1) s += __shfl_xor_sync(0xffffffffu, s, o);
        float inv = 1.0f / fmaxf(sqrtf(s), 1e-12f);
        if (row < n_total) {
            if (writeE) {
                g_E[row * D + j0] = e0;
                g_E[row * D + j1] = e1;
            }
            __stcs(&out[row * 4 * D + out_col + j0], e0 * inv);
            __stcs(&out[row * 4 * D + out_col + j1], e1 * inv);
        }
    }
}

extern "C" void kernel_launch(void* const* d_in, const int* in_sizes, int n_in,
                              void* d_out, int out_size) {
    const float* user = (const float*)d_in[0];
    const float* item = (const float*)d_in[1];
    const int*   erow = (const int*)d_in[2];
    const int*   ecol = (const int*)d_in[3];
    const float* eval = (const float*)d_in[4];
    const float* Wf   = (const float*)d_in[5];
    const float* bf   = (const float*)d_in[6];
    const float* Wb   = (const float*)d_in[7];
    const float* bb   = (const float*)d_in[8];
    float* out = (float*)d_out;

    int n_user = in_sizes[0] / D;
    int n_item = in_sizes[1] / D;
    int N  = n_user + n_item;
    int nE = in_sizes[2];

    // smem: 2*64*66 (weights) + 2*64*68 (fs/efs) floats = 68608 bytes -> 3 blocks/SM
    const int smem_bytes = (2 * 64 * WSTR + 2 * 64 * FSTR) * 4;
    cudaFuncSetAttribute(fused_kernel, cudaFuncAttributeMaxDynamicSharedMemorySize, smem_bytes);

    initE_kernel<<<(N * 16 + 255) / 256, 256>>>(user, item, out, n_user, N);
    zero_agg_kernel<<<(N * 16 + 255) / 256, 256>>>(N);

    for (int i = 0; i < 3; i++) {
        scatter_kernel<<<(nE * 16 + 255) / 256, 256>>>(erow, ecol, eval, nE);
        fused_kernel<<<(N + RPB - 1) / RPB, TPB, smem_bytes>>>(
            Wf + i * 4096, bf + i * 64, Wb + i * 4096, bb + i * 64,
            out, (i + 1) * 64, N, (i < 2) ? 1 : 0, (i < 2) ? 1 : 0);
    }
}